// round 15
// baseline (speedup 1.0000x reference)
#include <cuda_runtime.h>

#define N_NODES 500000
#define N_EDGES 16000000

// ---------------- scratch (device globals; no allocs allowed) ----------------
__device__ int       g_src[N_EDGES];     // 64 MB (decoded src, int64 input only)
__device__ int       g_dst[N_EDGES];     // 64 MB (decoded dst, int64 input only)
__device__ unsigned  g_deg[N_NODES];     // 2 MB
__device__ float     g_dinv[N_NODES];    // 2 MB
__device__ float2    g_xs[N_NODES];      // 4 MB  layer-1 prescaled raw features
__device__ float2    g_agg2[N_NODES];    // 4 MB  layer-1 accumulator
__device__ float4    g_xw[N_NODES];      // 8 MB  layer-2 prescaled
__device__ float4    g_agg[N_NODES];     // 8 MB  layer-2 accumulator
__device__ float2    g_xw2[N_NODES];     // 4 MB  layer-3 prescaled
__device__ int       g_is64;             // edge dtype flag

// ---------------- vector red helpers ----------------
__device__ __forceinline__ void red_add_f4(float4* p, float4 v) {
    asm volatile("red.global.add.v4.f32 [%0], {%1,%2,%3,%4};"
                 :: "l"(p), "f"(v.x), "f"(v.y), "f"(v.z), "f"(v.w) : "memory");
}
__device__ __forceinline__ void red_add_f2(float2* p, float2 v) {
    asm volatile("red.global.add.v2.f32 [%0], {%1,%2};"
                 :: "l"(p), "f"(v.x), "f"(v.y) : "memory");
}

// ---------------- detect dtype + zero degrees (fused) ----------------
__global__ void k_detect_zero(const int* __restrict__ e) {
    int i = blockIdx.x * blockDim.x + threadIdx.x;
    if (i < N_NODES) g_deg[i] = 0u;
    if (blockIdx.x == 0) {
        __shared__ int nz;
        if (threadIdx.x == 0) nz = 0;
        __syncthreads();
        int local = 0;
        #pragma unroll
        for (int m = 0; m < 16; m++) {
            int k = (int)((((unsigned)threadIdx.x * 16u + m) * 7919u) & (16u * 1024u * 1024u - 1u));
            if (e[2 * k + 1] != 0) local = 1;
        }
        if (local) atomicOr(&nz, 1);
        __syncthreads();
        if (threadIdx.x == 0) g_is64 = (nz == 0) ? 1 : 0;
    }
}

// Degree histogram (+ int64 decode). 8 edges/thread.
__global__ void k_prep_edges(const int* __restrict__ e) {
    int t = blockIdx.x * blockDim.x + threadIdx.x;   // edges 8t..8t+7
    if (8 * t >= N_EDGES) return;
    int4 d0, d1;
    if (g_is64) {
        const int4* e4 = (const int4*)e;
        int4 a0 = __ldcs(&e4[4 * t + 0]);
        int4 a1 = __ldcs(&e4[4 * t + 1]);
        int4 a2 = __ldcs(&e4[4 * t + 2]);
        int4 a3 = __ldcs(&e4[4 * t + 3]);
        int4 c0 = __ldcs(&e4[(N_EDGES / 2) + 4 * t + 0]);
        int4 c1 = __ldcs(&e4[(N_EDGES / 2) + 4 * t + 1]);
        int4 c2 = __ldcs(&e4[(N_EDGES / 2) + 4 * t + 2]);
        int4 c3 = __ldcs(&e4[(N_EDGES / 2) + 4 * t + 3]);
        ((int4*)g_src)[2 * t]     = make_int4(a0.x, a0.z, a1.x, a1.z);
        ((int4*)g_src)[2 * t + 1] = make_int4(a2.x, a2.z, a3.x, a3.z);
        d0 = make_int4(c0.x, c0.z, c1.x, c1.z);
        d1 = make_int4(c2.x, c2.z, c3.x, c3.z);
        ((int4*)g_dst)[2 * t]     = d0;
        ((int4*)g_dst)[2 * t + 1] = d1;
    } else {
        d0 = __ldcs(&((const int4*)e)[(N_EDGES / 4) + 2 * t]);
        d1 = __ldcs(&((const int4*)e)[(N_EDGES / 4) + 2 * t + 1]);
    }
    atomicAdd(&g_deg[d0.x], 1u);
    atomicAdd(&g_deg[d0.y], 1u);
    atomicAdd(&g_deg[d0.z], 1u);
    atomicAdd(&g_deg[d0.w], 1u);
    atomicAdd(&g_deg[d1.x], 1u);
    atomicAdd(&g_deg[d1.y], 1u);
    atomicAdd(&g_deg[d1.z], 1u);
    atomicAdd(&g_deg[d1.w], 1u);
}

// Layer-1 node stage: di = rsqrt(deg+1); xs = x*di (W1 deferred); agg2 = self.
__global__ void k_node1(const float* __restrict__ x) {
    int i = blockIdx.x * blockDim.x + threadIdx.x;
    if (i >= N_NODES) return;
    float di = rsqrtf((float)g_deg[i] + 1.0f);
    g_dinv[i] = di;
    float2 xi = ((const float2*)x)[i];
    float2 r = make_float2(xi.x * di, xi.y * di);
    g_xs[i]   = r;
    g_agg2[i] = r;
}

// Index fetch for 16-edges/thread passes: fills s[4], d[4] (int4 each).
#define LOAD_IDX16(e)                                                    \
    int4 s[4], d[4];                                                     \
    if (g_is64) {                                                        \
        const int4* sp = (const int4*)g_src;                             \
        const int4* dp = (const int4*)g_dst;                             \
        s[0] = __ldcs(&sp[4 * t + 0]);  s[1] = __ldcs(&sp[4 * t + 1]);   \
        s[2] = __ldcs(&sp[4 * t + 2]);  s[3] = __ldcs(&sp[4 * t + 3]);   \
        d[0] = __ldcs(&dp[4 * t + 0]);  d[1] = __ldcs(&dp[4 * t + 1]);   \
        d[2] = __ldcs(&dp[4 * t + 2]);  d[3] = __ldcs(&dp[4 * t + 3]);   \
    } else {                                                             \
        const int4* e4 = (const int4*)(e);                               \
        s[0] = __ldcs(&e4[4 * t + 0]);  s[1] = __ldcs(&e4[4 * t + 1]);   \
        s[2] = __ldcs(&e4[4 * t + 2]);  s[3] = __ldcs(&e4[4 * t + 3]);   \
        d[0] = __ldcs(&e4[(N_EDGES / 4) + 4 * t + 0]);                   \
        d[1] = __ldcs(&e4[(N_EDGES / 4) + 4 * t + 1]);                   \
        d[2] = __ldcs(&e4[(N_EDGES / 4) + 4 * t + 2]);                   \
        d[3] = __ldcs(&e4[(N_EDGES / 4) + 4 * t + 3]);                   \
    }

// One wave of 8 edges: 8 independent gathers then 8 fire-and-forget reds.
// (reds produce no registers, so the next wave's gathers overlap them.)
#define WAVE8_F2(TBL, ACC, si, sj, di_, dj)                              \
    {                                                                    \
        float2 v0 = TBL[si.x], v1 = TBL[si.y], v2 = TBL[si.z], v3 = TBL[si.w]; \
        float2 v4 = TBL[sj.x], v5 = TBL[sj.y], v6 = TBL[sj.z], v7 = TBL[sj.w]; \
        red_add_f2(&ACC[di_.x], v0); red_add_f2(&ACC[di_.y], v1);        \
        red_add_f2(&ACC[di_.z], v2); red_add_f2(&ACC[di_.w], v3);        \
        red_add_f2(&ACC[dj.x], v4);  red_add_f2(&ACC[dj.y], v5);         \
        red_add_f2(&ACC[dj.z], v6);  red_add_f2(&ACC[dj.w], v7);         \
    }

#define WAVE8_F4(TBL, ACC, si, sj, di_, dj)                              \
    {                                                                    \
        float4 v0 = TBL[si.x], v1 = TBL[si.y], v2 = TBL[si.z], v3 = TBL[si.w]; \
        float4 v4 = TBL[sj.x], v5 = TBL[sj.y], v6 = TBL[sj.z], v7 = TBL[sj.w]; \
        red_add_f4(&ACC[di_.x], v0); red_add_f4(&ACC[di_.y], v1);        \
        red_add_f4(&ACC[di_.z], v2); red_add_f4(&ACC[di_.w], v3);        \
        red_add_f4(&ACC[dj.x], v4);  red_add_f4(&ACC[dj.y], v5);         \
        red_add_f4(&ACC[dj.z], v6);  red_add_f4(&ACC[dj.w], v7);         \
    }

// Layer-1 edge pass: 2-wide, 16 edges/thread.  (capture slot #4)
__global__ void __launch_bounds__(256) k_edge1(const int* __restrict__ e) {
    int t = blockIdx.x * blockDim.x + threadIdx.x;
    if (16 * t >= N_EDGES) return;
    LOAD_IDX16(e)
    WAVE8_F2(g_xs, g_agg2, s[0], s[1], d[0], d[1])
    WAVE8_F2(g_xs, g_agg2, s[2], s[3], d[2], d[3])
}

// Layer-2 node stage: apply deferred W1 + b1 + tanh; xws2 = (h@W2)*di.
__global__ void k_node2(const float* __restrict__ W1, const float* __restrict__ b1,
                        const float* __restrict__ W2) {
    int i = blockIdx.x * blockDim.x + threadIdx.x;
    if (i >= N_NODES) return;
    float di = g_dinv[i];
    float2 a = g_agg2[i];
    float tx = a.x * di, ty = a.y * di;
    float hx = tanhf(tx * W1[0] + ty * W1[4] + b1[0]);
    float hy = tanhf(tx * W1[1] + ty * W1[5] + b1[1]);
    float hz = tanhf(tx * W1[2] + ty * W1[6] + b1[2]);
    float hw = tanhf(tx * W1[3] + ty * W1[7] + b1[3]);
    float4 r;
    r.x = (hx * W2[0] + hy * W2[4] + hz * W2[8]  + hw * W2[12]) * di;
    r.y = (hx * W2[1] + hy * W2[5] + hz * W2[9]  + hw * W2[13]) * di;
    r.z = (hx * W2[2] + hy * W2[6] + hz * W2[10] + hw * W2[14]) * di;
    r.w = (hx * W2[3] + hy * W2[7] + hz * W2[11] + hw * W2[15]) * di;
    g_xw[i]  = r;
    g_agg[i] = r;
}

// Layer-2 edge pass: 4-wide, 16 edges/thread (two waves cap live payload at 8xfloat4).
__global__ void __launch_bounds__(256) k_edge4(const int* __restrict__ e) {
    int t = blockIdx.x * blockDim.x + threadIdx.x;
    if (16 * t >= N_EDGES) return;
    LOAD_IDX16(e)
    WAVE8_F4(g_xw, g_agg, s[0], s[1], d[0], d[1])
    WAVE8_F4(g_xw, g_agg, s[2], s[3], d[2], d[3])
}

// Layer-3 node stage: h = tanh(agg*di + b2); xws3 = (h@W3)*di; out = self term.
__global__ void k_node3(const float* __restrict__ W3, const float* __restrict__ b2,
                        float2* __restrict__ out) {
    int i = blockIdx.x * blockDim.x + threadIdx.x;
    if (i >= N_NODES) return;
    float di = g_dinv[i];
    float4 a = g_agg[i];
    float hx = tanhf(a.x * di + b2[0]);
    float hy = tanhf(a.y * di + b2[1]);
    float hz = tanhf(a.z * di + b2[2]);
    float hw = tanhf(a.w * di + b2[3]);
    float2 r;
    r.x = (hx * W3[0] + hy * W3[2] + hz * W3[4] + hw * W3[6]) * di;
    r.y = (hx * W3[1] + hy * W3[3] + hz * W3[5] + hw * W3[7]) * di;
    g_xw2[i] = r;
    out[i]   = r;
}

// Layer-3 edge pass: 2-wide, 16 edges/thread, accumulating into d_out.
__global__ void __launch_bounds__(256) k_edge2(const int* __restrict__ e,
                                               float2* __restrict__ out) {
    int t = blockIdx.x * blockDim.x + threadIdx.x;
    if (16 * t >= N_EDGES) return;
    LOAD_IDX16(e)
    WAVE8_F2(g_xw2, out, s[0], s[1], d[0], d[1])
    WAVE8_F2(g_xw2, out, s[2], s[3], d[2], d[3])
}

// Final scale + bias: out_i = agg_i * dinv_i + b3.
__global__ void k_finalize(float2* __restrict__ out, const float* __restrict__ b3) {
    int i = blockIdx.x * blockDim.x + threadIdx.x;
    if (i >= N_NODES) return;
    float di = g_dinv[i];
    float2 a = out[i];
    a.x = a.x * di + b3[0];
    a.y = a.y * di + b3[1];
    out[i] = a;
}

// ---------------- launch ----------------
extern "C" void kernel_launch(void* const* d_in, const int* in_sizes, int n_in,
                              void* d_out, int out_size) {
    const float* x  = (const float*)d_in[0];
    const int*   e  = (const int*)d_in[1];
    const float* W1 = (const float*)d_in[2];
    const float* b1 = (const float*)d_in[3];
    const float* W2 = (const float*)d_in[4];
    const float* b2 = (const float*)d_in[5];
    const float* W3 = (const float*)d_in[6];
    const float* b3 = (const float*)d_in[7];
    float2* out = (float2*)d_out;

    const int TB = 256;
    const int gNode   = (N_NODES + TB - 1) / TB;
    const int gEdge8  = (N_EDGES / 8 + TB - 1) / TB;
    const int gEdge16 = (N_EDGES / 16 + TB - 1) / TB;

    k_detect_zero<<<gNode, TB>>>(e);        // launch 1
    k_prep_edges<<<gEdge8, TB>>>(e);        // launch 2

    k_node1<<<gNode, TB>>>(x);              // launch 3
    k_edge1<<<gEdge16, TB>>>(e);            // launch 4  <-- ncu capture slot

    k_node2<<<gNode, TB>>>(W1, b1, W2);
    k_edge4<<<gEdge16, TB>>>(e);

    k_node3<<<gNode, TB>>>(W3, b2, out);
    k_edge2<<<gEdge16, TB>>>(e, out);
    k_finalize<<<gNode, TB>>>(out, b3);
}

// round 16
// speedup vs baseline: 1.0445x; 1.0445x over previous
#include <cuda_runtime.h>

#define N_NODES 500000
#define N_EDGES 16000000

// ---------------- scratch (device globals; no allocs allowed) ----------------
__device__ int       g_src[N_EDGES];     // 64 MB (decoded src, int64 input only)
__device__ int       g_dst[N_EDGES];     // 64 MB (decoded dst, int64 input only)
__device__ unsigned  g_deg[N_NODES];     // 2 MB
__device__ float     g_dinv[N_NODES];    // 2 MB
__device__ float2    g_xs[N_NODES];      // 4 MB  layer-1 prescaled raw features
__device__ float2    g_agg2[N_NODES];    // 4 MB  layer-1 accumulator
__device__ float4    g_xw[N_NODES];      // 8 MB  layer-2 prescaled
__device__ float4    g_agg[N_NODES];     // 8 MB  layer-2 accumulator
__device__ float2    g_xw2[N_NODES];     // 4 MB  layer-3 prescaled
__device__ int       g_is64;             // edge dtype flag

// ---------------- vector red helpers ----------------
__device__ __forceinline__ void red_add_f4(float4* p, float4 v) {
    asm volatile("red.global.add.v4.f32 [%0], {%1,%2,%3,%4};"
                 :: "l"(p), "f"(v.x), "f"(v.y), "f"(v.z), "f"(v.w) : "memory");
}
__device__ __forceinline__ void red_add_f2(float2* p, float2 v) {
    asm volatile("red.global.add.v2.f32 [%0], {%1,%2};"
                 :: "l"(p), "f"(v.x), "f"(v.y) : "memory");
}

// ---------------- detect dtype + zero degrees (fused; one launch) -------------
__global__ void k_detect_zero(const int* __restrict__ e) {
    int i = blockIdx.x * blockDim.x + threadIdx.x;
    if (i < N_NODES) g_deg[i] = 0u;
    if (blockIdx.x == 0) {
        __shared__ int nz;
        if (threadIdx.x == 0) nz = 0;
        __syncthreads();
        int local = 0;
        #pragma unroll
        for (int m = 0; m < 16; m++) {
            int k = (int)((((unsigned)threadIdx.x * 16u + m) * 7919u) & (16u * 1024u * 1024u - 1u));
            if (e[2 * k + 1] != 0) local = 1;
        }
        if (local) atomicOr(&nz, 1);
        __syncthreads();
        if (threadIdx.x == 0) g_is64 = (nz == 0) ? 1 : 0;
    }
}

// Degree histogram (+ int64 -> int32 decode into scratch when needed).
__global__ void k_prep_edges(const int* __restrict__ e) {
    int t = blockIdx.x * blockDim.x + threadIdx.x;   // edges 4t..4t+3
    if (4 * t >= N_EDGES) return;
    int4 d;
    if (g_is64) {
        const int4* e4 = (const int4*)e;
        int4 a = __ldcs(&e4[2 * t]);
        int4 b = __ldcs(&e4[2 * t + 1]);
        int4 c = __ldcs(&e4[(N_EDGES / 2) + 2 * t]);
        int4 f = __ldcs(&e4[(N_EDGES / 2) + 2 * t + 1]);
        ((int4*)g_src)[t] = make_int4(a.x, a.z, b.x, b.z);
        d = make_int4(c.x, c.z, f.x, f.z);
        ((int4*)g_dst)[t] = d;
    } else {
        d = __ldcs(&((const int4*)e)[(N_EDGES / 4) + t]);
    }
    atomicAdd(&g_deg[d.x], 1u);
    atomicAdd(&g_deg[d.y], 1u);
    atomicAdd(&g_deg[d.z], 1u);
    atomicAdd(&g_deg[d.w], 1u);
}

// Layer-1 node stage: di = rsqrt(deg+1); xs = x*di (W1 deferred by linearity);
// agg2 init = self term.
__global__ void k_node1(const float* __restrict__ x) {
    int i = blockIdx.x * blockDim.x + threadIdx.x;
    if (i >= N_NODES) return;
    float di = rsqrtf((float)g_deg[i] + 1.0f);
    g_dinv[i] = di;
    float2 xi = ((const float2*)x)[i];
    float2 r = make_float2(xi.x * di, xi.y * di);
    g_xs[i]   = r;
    g_agg2[i] = r;
}

// Shared index-fetch for 8-edges/thread passes.
#define LOAD_IDX8(e)                                                     \
    int4 s0, s1, d0, d1;                                                 \
    if (g_is64) {                                                        \
        const int4* sp = (const int4*)g_src;                             \
        const int4* dp = (const int4*)g_dst;                             \
        s0 = __ldcs(&sp[2 * t]);  s1 = __ldcs(&sp[2 * t + 1]);           \
        d0 = __ldcs(&dp[2 * t]);  d1 = __ldcs(&dp[2 * t + 1]);           \
    } else {                                                             \
        const int4* e4 = (const int4*)(e);                               \
        s0 = __ldcs(&e4[2 * t]);  s1 = __ldcs(&e4[2 * t + 1]);           \
        d0 = __ldcs(&e4[(N_EDGES / 4) + 2 * t]);                         \
        d1 = __ldcs(&e4[(N_EDGES / 4) + 2 * t + 1]);                     \
    }

// Layer-1 edge pass: 2-wide. agg2[dst] += xs[src].  (capture slot #4)
__global__ void k_edge1(const int* __restrict__ e) {
    int t = blockIdx.x * blockDim.x + threadIdx.x;
    if (8 * t >= N_EDGES) return;
    LOAD_IDX8(e)
    float2 v0 = g_xs[s0.x];
    float2 v1 = g_xs[s0.y];
    float2 v2 = g_xs[s0.z];
    float2 v3 = g_xs[s0.w];
    float2 v4 = g_xs[s1.x];
    float2 v5 = g_xs[s1.y];
    float2 v6 = g_xs[s1.z];
    float2 v7 = g_xs[s1.w];
    red_add_f2(&g_agg2[d0.x], v0);
    red_add_f2(&g_agg2[d0.y], v1);
    red_add_f2(&g_agg2[d0.z], v2);
    red_add_f2(&g_agg2[d0.w], v3);
    red_add_f2(&g_agg2[d1.x], v4);
    red_add_f2(&g_agg2[d1.y], v5);
    red_add_f2(&g_agg2[d1.z], v6);
    red_add_f2(&g_agg2[d1.w], v7);
}

// Layer-2 node stage: apply deferred W1 + b1 + tanh; xws2 = (h@W2)*di.
__global__ void k_node2(const float* __restrict__ W1, const float* __restrict__ b1,
                        const float* __restrict__ W2) {
    int i = blockIdx.x * blockDim.x + threadIdx.x;
    if (i >= N_NODES) return;
    float di = g_dinv[i];
    float2 a = g_agg2[i];
    float tx = a.x * di, ty = a.y * di;
    float hx = tanhf(tx * W1[0] + ty * W1[4] + b1[0]);
    float hy = tanhf(tx * W1[1] + ty * W1[5] + b1[1]);
    float hz = tanhf(tx * W1[2] + ty * W1[6] + b1[2]);
    float hw = tanhf(tx * W1[3] + ty * W1[7] + b1[3]);
    float4 r;
    r.x = (hx * W2[0] + hy * W2[4] + hz * W2[8]  + hw * W2[12]) * di;
    r.y = (hx * W2[1] + hy * W2[5] + hz * W2[9]  + hw * W2[13]) * di;
    r.z = (hx * W2[2] + hy * W2[6] + hz * W2[10] + hw * W2[14]) * di;
    r.w = (hx * W2[3] + hy * W2[7] + hz * W2[11] + hw * W2[15]) * di;
    g_xw[i]  = r;
    g_agg[i] = r;
}

// Layer-2 edge pass: 4-wide. agg[dst] += xw[src].
__global__ void k_edge4(const int* __restrict__ e) {
    int t = blockIdx.x * blockDim.x + threadIdx.x;
    if (8 * t >= N_EDGES) return;
    LOAD_IDX8(e)
    float4 v0 = g_xw[s0.x];
    float4 v1 = g_xw[s0.y];
    float4 v2 = g_xw[s0.z];
    float4 v3 = g_xw[s0.w];
    float4 v4 = g_xw[s1.x];
    float4 v5 = g_xw[s1.y];
    float4 v6 = g_xw[s1.z];
    float4 v7 = g_xw[s1.w];
    red_add_f4(&g_agg[d0.x], v0);
    red_add_f4(&g_agg[d0.y], v1);
    red_add_f4(&g_agg[d0.z], v2);
    red_add_f4(&g_agg[d0.w], v3);
    red_add_f4(&g_agg[d1.x], v4);
    red_add_f4(&g_agg[d1.y], v5);
    red_add_f4(&g_agg[d1.z], v6);
    red_add_f4(&g_agg[d1.w], v7);
}

// Layer-3 node stage: h = tanh(agg*di + b2); xws3 = (h@W3)*di; out = self term.
__global__ void k_node3(const float* __restrict__ W3, const float* __restrict__ b2,
                        float2* __restrict__ out) {
    int i = blockIdx.x * blockDim.x + threadIdx.x;
    if (i >= N_NODES) return;
    float di = g_dinv[i];
    float4 a = g_agg[i];
    float hx = tanhf(a.x * di + b2[0]);
    float hy = tanhf(a.y * di + b2[1]);
    float hz = tanhf(a.z * di + b2[2]);
    float hw = tanhf(a.w * di + b2[3]);
    float2 r;
    r.x = (hx * W3[0] + hy * W3[2] + hz * W3[4] + hw * W3[6]) * di;
    r.y = (hx * W3[1] + hy * W3[3] + hz * W3[5] + hw * W3[7]) * di;
    g_xw2[i] = r;
    out[i]   = r;
}

// Layer-3 edge pass: 2-wide, accumulating straight into d_out.
__global__ void k_edge2(const int* __restrict__ e, float2* __restrict__ out) {
    int t = blockIdx.x * blockDim.x + threadIdx.x;
    if (8 * t >= N_EDGES) return;
    LOAD_IDX8(e)
    float2 v0 = g_xw2[s0.x];
    float2 v1 = g_xw2[s0.y];
    float2 v2 = g_xw2[s0.z];
    float2 v3 = g_xw2[s0.w];
    float2 v4 = g_xw2[s1.x];
    float2 v5 = g_xw2[s1.y];
    float2 v6 = g_xw2[s1.z];
    float2 v7 = g_xw2[s1.w];
    red_add_f2(&out[d0.x], v0);
    red_add_f2(&out[d0.y], v1);
    red_add_f2(&out[d0.z], v2);
    red_add_f2(&out[d0.w], v3);
    red_add_f2(&out[d1.x], v4);
    red_add_f2(&out[d1.y], v5);
    red_add_f2(&out[d1.z], v6);
    red_add_f2(&out[d1.w], v7);
}

// Final scale + bias: out_i = agg_i * dinv_i + b3 (no tanh on last layer).
__global__ void k_finalize(float2* __restrict__ out, const float* __restrict__ b3) {
    int i = blockIdx.x * blockDim.x + threadIdx.x;
    if (i >= N_NODES) return;
    float di = g_dinv[i];
    float2 a = out[i];
    a.x = a.x * di + b3[0];
    a.y = a.y * di + b3[1];
    out[i] = a;
}

// ---------------- launch ----------------
extern "C" void kernel_launch(void* const* d_in, const int* in_sizes, int n_in,
                              void* d_out, int out_size) {
    const float* x  = (const float*)d_in[0];
    const int*   e  = (const int*)d_in[1];
    const float* W1 = (const float*)d_in[2];
    const float* b1 = (const float*)d_in[3];
    const float* W2 = (const float*)d_in[4];
    const float* b2 = (const float*)d_in[5];
    const float* W3 = (const float*)d_in[6];
    const float* b3 = (const float*)d_in[7];
    float2* out = (float2*)d_out;

    const int TB = 256;
    const int gNode  = (N_NODES + TB - 1) / TB;
    const int gEdge4 = (N_EDGES / 4 + TB - 1) / TB;
    const int gEdge8 = (N_EDGES / 8 + TB - 1) / TB;

    k_detect_zero<<<gNode, TB>>>(e);        // launch 1
    k_prep_edges<<<gEdge4, TB>>>(e);        // launch 2

    k_node1<<<gNode, TB>>>(x);              // launch 3
    k_edge1<<<gEdge8, TB>>>(e);             // launch 4  <-- ncu capture slot

    k_node2<<<gNode, TB>>>(W1, b1, W2);
    k_edge4<<<gEdge8, TB>>>(e);

    k_node3<<<gNode, TB>>>(W3, b2, out);
    k_edge2<<<gEdge8, TB>>>(e, out);
    k_finalize<<<gNode, TB>>>(out, b3);
}

// round 17
// speedup vs baseline: 1.0464x; 1.0018x over previous
#include <cuda_runtime.h>

#define N_NODES 500000
#define N_EDGES 16000000

// ---------------- scratch (device globals; no allocs allowed) ----------------
__device__ int       g_src[N_EDGES];     // 64 MB (decoded src, int64 input only)
__device__ int       g_dst[N_EDGES];     // 64 MB (decoded dst, int64 input only)
__device__ unsigned  g_deg[N_NODES];     // 2 MB
__device__ float     g_dinv[N_NODES];    // 2 MB
__device__ float2    g_xs[N_NODES];      // 4 MB  layer-1 prescaled raw features
__device__ float2    g_agg2[N_NODES];    // 4 MB  layer-1 accumulator
__device__ float4    g_xw[N_NODES];      // 8 MB  layer-2 prescaled
__device__ float4    g_agg[N_NODES];     // 8 MB  layer-2 accumulator
__device__ float2    g_xw2[N_NODES];     // 4 MB  layer-3 prescaled
__device__ int       g_is64;             // edge dtype flag

// ---------------- helpers ----------------
__device__ __forceinline__ void red_add_f4(float4* p, float4 v) {
    asm volatile("red.global.add.v4.f32 [%0], {%1,%2,%3,%4};"
                 :: "l"(p), "f"(v.x), "f"(v.y), "f"(v.z), "f"(v.w) : "memory");
}
__device__ __forceinline__ void red_add_f2(float2* p, float2 v) {
    asm volatile("red.global.add.v2.f32 [%0], {%1,%2};"
                 :: "l"(p), "f"(v.x), "f"(v.y) : "memory");
}
// Single-instruction HW tanh (sm_75+). Max err ~1e-5, far under the 1e-3 gate.
__device__ __forceinline__ float tanh_fast(float x) {
    float r;
    asm("tanh.approx.f32 %0, %1;" : "=f"(r) : "f"(x));
    return r;
}

// ---------------- detect dtype + zero degrees (fused; one launch) -------------
__global__ void k_detect_zero(const int* __restrict__ e) {
    int i = blockIdx.x * blockDim.x + threadIdx.x;
    if (i < N_NODES) g_deg[i] = 0u;
    if (blockIdx.x == 0) {
        __shared__ int nz;
        if (threadIdx.x == 0) nz = 0;
        __syncthreads();
        int local = 0;
        #pragma unroll
        for (int m = 0; m < 16; m++) {
            int k = (int)((((unsigned)threadIdx.x * 16u + m) * 7919u) & (16u * 1024u * 1024u - 1u));
            if (e[2 * k + 1] != 0) local = 1;
        }
        if (local) atomicOr(&nz, 1);
        __syncthreads();
        if (threadIdx.x == 0) g_is64 = (nz == 0) ? 1 : 0;
    }
}

// Degree histogram (+ int64 -> int32 decode into scratch when needed).
__global__ void k_prep_edges(const int* __restrict__ e) {
    int t = blockIdx.x * blockDim.x + threadIdx.x;   // edges 4t..4t+3
    if (4 * t >= N_EDGES) return;
    int4 d;
    if (g_is64) {
        const int4* e4 = (const int4*)e;
        int4 a = __ldcs(&e4[2 * t]);
        int4 b = __ldcs(&e4[2 * t + 1]);
        int4 c = __ldcs(&e4[(N_EDGES / 2) + 2 * t]);
        int4 f = __ldcs(&e4[(N_EDGES / 2) + 2 * t + 1]);
        ((int4*)g_src)[t] = make_int4(a.x, a.z, b.x, b.z);
        d = make_int4(c.x, c.z, f.x, f.z);
        ((int4*)g_dst)[t] = d;
    } else {
        d = __ldcs(&((const int4*)e)[(N_EDGES / 4) + t]);
    }
    atomicAdd(&g_deg[d.x], 1u);
    atomicAdd(&g_deg[d.y], 1u);
    atomicAdd(&g_deg[d.z], 1u);
    atomicAdd(&g_deg[d.w], 1u);
}

// Layer-1 node stage: di = rsqrt(deg+1); xs = x*di (W1 deferred by linearity);
// agg2 init = self term.
__global__ void k_node1(const float* __restrict__ x) {
    int i = blockIdx.x * blockDim.x + threadIdx.x;
    if (i >= N_NODES) return;
    float di = rsqrtf((float)g_deg[i] + 1.0f);
    g_dinv[i] = di;
    float2 xi = ((const float2*)x)[i];
    float2 r = make_float2(xi.x * di, xi.y * di);
    g_xs[i]   = r;
    g_agg2[i] = r;
}

// Shared index-fetch for 8-edges/thread passes.
#define LOAD_IDX8(e)                                                     \
    int4 s0, s1, d0, d1;                                                 \
    if (g_is64) {                                                        \
        const int4* sp = (const int4*)g_src;                             \
        const int4* dp = (const int4*)g_dst;                             \
        s0 = __ldcs(&sp[2 * t]);  s1 = __ldcs(&sp[2 * t + 1]);           \
        d0 = __ldcs(&dp[2 * t]);  d1 = __ldcs(&dp[2 * t + 1]);           \
    } else {                                                             \
        const int4* e4 = (const int4*)(e);                               \
        s0 = __ldcs(&e4[2 * t]);  s1 = __ldcs(&e4[2 * t + 1]);           \
        d0 = __ldcs(&e4[(N_EDGES / 4) + 2 * t]);                         \
        d1 = __ldcs(&e4[(N_EDGES / 4) + 2 * t + 1]);                     \
    }

// Layer-1 edge pass: 2-wide. agg2[dst] += xs[src].  (capture slot #4)
__global__ void k_edge1(const int* __restrict__ e) {
    int t = blockIdx.x * blockDim.x + threadIdx.x;
    if (8 * t >= N_EDGES) return;
    LOAD_IDX8(e)
    float2 v0 = g_xs[s0.x];
    float2 v1 = g_xs[s0.y];
    float2 v2 = g_xs[s0.z];
    float2 v3 = g_xs[s0.w];
    float2 v4 = g_xs[s1.x];
    float2 v5 = g_xs[s1.y];
    float2 v6 = g_xs[s1.z];
    float2 v7 = g_xs[s1.w];
    red_add_f2(&g_agg2[d0.x], v0);
    red_add_f2(&g_agg2[d0.y], v1);
    red_add_f2(&g_agg2[d0.z], v2);
    red_add_f2(&g_agg2[d0.w], v3);
    red_add_f2(&g_agg2[d1.x], v4);
    red_add_f2(&g_agg2[d1.y], v5);
    red_add_f2(&g_agg2[d1.z], v6);
    red_add_f2(&g_agg2[d1.w], v7);
}

// Layer-2 node stage: apply deferred W1 + b1 + tanh; xws2 = (h@W2)*di.
__global__ void k_node2(const float* __restrict__ W1, const float* __restrict__ b1,
                        const float* __restrict__ W2) {
    int i = blockIdx.x * blockDim.x + threadIdx.x;
    if (i >= N_NODES) return;
    float di = g_dinv[i];
    float2 a = g_agg2[i];
    float tx = a.x * di, ty = a.y * di;
    float hx = tanh_fast(tx * W1[0] + ty * W1[4] + b1[0]);
    float hy = tanh_fast(tx * W1[1] + ty * W1[5] + b1[1]);
    float hz = tanh_fast(tx * W1[2] + ty * W1[6] + b1[2]);
    float hw = tanh_fast(tx * W1[3] + ty * W1[7] + b1[3]);
    float4 r;
    r.x = (hx * W2[0] + hy * W2[4] + hz * W2[8]  + hw * W2[12]) * di;
    r.y = (hx * W2[1] + hy * W2[5] + hz * W2[9]  + hw * W2[13]) * di;
    r.z = (hx * W2[2] + hy * W2[6] + hz * W2[10] + hw * W2[14]) * di;
    r.w = (hx * W2[3] + hy * W2[7] + hz * W2[11] + hw * W2[15]) * di;
    g_xw[i]  = r;
    g_agg[i] = r;
}

// Layer-2 edge pass: 4-wide. agg[dst] += xw[src].
__global__ void k_edge4(const int* __restrict__ e) {
    int t = blockIdx.x * blockDim.x + threadIdx.x;
    if (8 * t >= N_EDGES) return;
    LOAD_IDX8(e)
    float4 v0 = g_xw[s0.x];
    float4 v1 = g_xw[s0.y];
    float4 v2 = g_xw[s0.z];
    float4 v3 = g_xw[s0.w];
    float4 v4 = g_xw[s1.x];
    float4 v5 = g_xw[s1.y];
    float4 v6 = g_xw[s1.z];
    float4 v7 = g_xw[s1.w];
    red_add_f4(&g_agg[d0.x], v0);
    red_add_f4(&g_agg[d0.y], v1);
    red_add_f4(&g_agg[d0.z], v2);
    red_add_f4(&g_agg[d0.w], v3);
    red_add_f4(&g_agg[d1.x], v4);
    red_add_f4(&g_agg[d1.y], v5);
    red_add_f4(&g_agg[d1.z], v6);
    red_add_f4(&g_agg[d1.w], v7);
}

// Layer-3 node stage: h = tanh(agg*di + b2); xws3 = (h@W3)*di; out = self term.
__global__ void k_node3(const float* __restrict__ W3, const float* __restrict__ b2,
                        float2* __restrict__ out) {
    int i = blockIdx.x * blockDim.x + threadIdx.x;
    if (i >= N_NODES) return;
    float di = g_dinv[i];
    float4 a = g_agg[i];
    float hx = tanh_fast(a.x * di + b2[0]);
    float hy = tanh_fast(a.y * di + b2[1]);
    float hz = tanh_fast(a.z * di + b2[2]);
    float hw = tanh_fast(a.w * di + b2[3]);
    float2 r;
    r.x = (hx * W3[0] + hy * W3[2] + hz * W3[4] + hw * W3[6]) * di;
    r.y = (hx * W3[1] + hy * W3[3] + hz * W3[5] + hw * W3[7]) * di;
    g_xw2[i] = r;
    out[i]   = r;
}

// Layer-3 edge pass: 2-wide, accumulating straight into d_out.
__global__ void k_edge2(const int* __restrict__ e, float2* __restrict__ out) {
    int t = blockIdx.x * blockDim.x + threadIdx.x;
    if (8 * t >= N_EDGES) return;
    LOAD_IDX8(e)
    float2 v0 = g_xw2[s0.x];
    float2 v1 = g_xw2[s0.y];
    float2 v2 = g_xw2[s0.z];
    float2 v3 = g_xw2[s0.w];
    float2 v4 = g_xw2[s1.x];
    float2 v5 = g_xw2[s1.y];
    float2 v6 = g_xw2[s1.z];
    float2 v7 = g_xw2[s1.w];
    red_add_f2(&out[d0.x], v0);
    red_add_f2(&out[d0.y], v1);
    red_add_f2(&out[d0.z], v2);
    red_add_f2(&out[d0.w], v3);
    red_add_f2(&out[d1.x], v4);
    red_add_f2(&out[d1.y], v5);
    red_add_f2(&out[d1.z], v6);
    red_add_f2(&out[d1.w], v7);
}

// Final scale + bias: out_i = agg_i * dinv_i + b3 (no tanh on last layer).
__global__ void k_finalize(float2* __restrict__ out, const float* __restrict__ b3) {
    int i = blockIdx.x * blockDim.x + threadIdx.x;
    if (i >= N_NODES) return;
    float di = g_dinv[i];
    float2 a = out[i];
    a.x = a.x * di + b3[0];
    a.y = a.y * di + b3[1];
    out[i] = a;
}

// ---------------- launch ----------------
extern "C" void kernel_launch(void* const* d_in, const int* in_sizes, int n_in,
                              void* d_out, int out_size) {
    const float* x  = (const float*)d_in[0];
    const int*   e  = (const int*)d_in[1];
    const float* W1 = (const float*)d_in[2];
    const float* b1 = (const float*)d_in[3];
    const float* W2 = (const float*)d_in[4];
    const float* b2 = (const float*)d_in[5];
    const float* W3 = (const float*)d_in[6];
    const float* b3 = (const float*)d_in[7];
    float2* out = (float2*)d_out;

    const int TB = 256;
    const int gNode  = (N_NODES + TB - 1) / TB;
    const int gEdge4 = (N_EDGES / 4 + TB - 1) / TB;
    const int gEdge8 = (N_EDGES / 8 + TB - 1) / TB;

    k_detect_zero<<<gNode, TB>>>(e);        // launch 1
    k_prep_edges<<<gEdge4, TB>>>(e);        // launch 2

    k_node1<<<gNode, TB>>>(x);              // launch 3
    k_edge1<<<gEdge8, TB>>>(e);             // launch 4  <-- ncu capture slot

    k_node2<<<gNode, TB>>>(W1, b1, W2);
    k_edge4<<<gEdge8, TB>>>(e);

    k_node3<<<gNode, TB>>>(W3, b2, out);
    k_edge2<<<gEdge8, TB>>>(e, out);
    k_finalize<<<gNode, TB>>>(out, b3);
}